// round 11
// baseline (speedup 1.0000x reference)
#include <cuda_runtime.h>
#include <cstdint>

// Problem constants (match reference setup_inputs)
#define NN   500000
#define DD   256
#define GG   1024
#define HH   128
#define LL   128
#define OC   896      // 3*D + D/2
#define M1   32       // nodes per tile

// ---------------- device scratch (no cudaMalloc allowed) ----------------
__device__ float        g_denom[GG];         // softmax denominator per segment
__device__ float        g_cnt[GG];           // node count per segment
// packed weights: g_wP[d4*256 + col] = float4{ w(4*d4+0,col), ..., w(4*d4+3,col) }
// col<128 -> w1 column, col>=128 -> lp_w column. Warp loads are 512B contiguous.
__device__ __align__(16) float g_wP[256 * 256];
__device__ float        g_bs[256];           // [b1 ; lp_b]

// ---------------- helpers ----------------
__device__ __forceinline__ unsigned enc_f(float f) {
    unsigned u = __float_as_uint(f);
    return (u & 0x80000000u) ? ~u : (u | 0x80000000u);
}
__device__ __forceinline__ float dec_f(unsigned u) {
    return (u & 0x80000000u) ? __uint_as_float(u & 0x7FFFFFFFu)
                             : __uint_as_float(~u);
}
#define ENC_NEG_INF 0x007FFFFFu   // enc(-inf)

__device__ __forceinline__ float gelu_exact(float z) {
    return 0.5f * z * (1.0f + erff(z * 0.7071067811865476f));
}

// packed f32x2 FMA (FFMA2) — only reachable via PTX
__device__ __forceinline__ unsigned long long ffma2(unsigned long long a,
                                                    unsigned long long b,
                                                    unsigned long long c) {
    unsigned long long d;
    asm("fma.rn.f32x2 %0, %1, %2, %3;" : "=l"(d) : "l"(a), "l"(b), "l"(c));
    return d;
}
__device__ __forceinline__ float2 unpk(unsigned long long v) {
    float2 f;
    asm("mov.b64 {%0, %1}, %2;" : "=f"(f.x), "=f"(f.y) : "l"(v));
    return f;
}

// ---------------- kernel 0: init accumulators (runs every launch/replay) ----
__global__ void k_init(float* __restrict__ out) {
    int i = blockIdx.x * blockDim.x + threadIdx.x;
    int total = GG * OC;
    if (i < total) {
        int c = i % OC;
        if (c >= DD && c < 2 * DD)
            ((unsigned*)out)[i] = ENC_NEG_INF;   // max-pool region, encoded
        else
            out[i] = 0.0f;
    }
    if (i < GG) {
        g_cnt[i]   = 0.0f;
        g_denom[i] = 0.0f;
    }
}

// ---------------- kernel T: pack weights ----------------
// grid=64 (d4), block=256 (col). Reads of w1/lp_w are coalesced across col.
__global__ void k_prep(const float* __restrict__ w1, const float* __restrict__ lp_w,
                       const float* __restrict__ b1, const float* __restrict__ lp_b) {
    int d4  = blockIdx.x;     // 0..63
    int col = threadIdx.x;    // 0..255
    float4 v;
    if (col < HH) {
        v.x = w1[(4 * d4 + 0) * HH + col];
        v.y = w1[(4 * d4 + 1) * HH + col];
        v.z = w1[(4 * d4 + 2) * HH + col];
        v.w = w1[(4 * d4 + 3) * HH + col];
    } else {
        int c = col - HH;
        v.x = lp_w[(4 * d4 + 0) * LL + c];
        v.y = lp_w[(4 * d4 + 1) * LL + c];
        v.z = lp_w[(4 * d4 + 2) * LL + c];
        v.w = lp_w[(4 * d4 + 3) * LL + c];
    }
    ((float4*)g_wP)[d4 * 256 + col] = v;
    if (d4 == 0)
        g_bs[col] = (col < HH) ? b1[col] : lp_b[col - HH];
}

// ---------------- fused kernel: MLPs + all four pools in one x pass --------
// Static shared: 32768 (sX) + 512 (sGp) + 128 (sE) + 128 (sb) = 33536 B < 48K.
__global__ __launch_bounds__(256, 2)
void k_fused(const float* __restrict__ x, const int* __restrict__ batch,
             const float* __restrict__ w2, const float* __restrict__ b2,
             float* __restrict__ out, int N) {
    __shared__ __align__(16) float sX[M1 * 256];   // x tile (persists whole kernel)
    __shared__ float sGp[M1 * 4];                  // per-warp partial gate sums
    __shared__ float sE[M1];                       // exp(gate) per node
    __shared__ int   sb[M1];

    const int  tid  = threadIdx.x;
    const int  lane = tid & 31;
    const long base = (long)blockIdx.x * M1;

    // --- load x tile (float4, coalesced), zero-pad tail ---
    for (int i = tid; i < M1 * 64; i += 256) {
        int  m    = i >> 6;
        int  q    = i & 63;
        long node = base + m;
        float4 v  = make_float4(0.f, 0.f, 0.f, 0.f);
        if (node < N) v = ((const float4*)x)[node * 64 + q];
        ((float4*)sX)[i] = v;
    }
    if (tid < M1) {
        long node = base + tid;
        sb[tid] = (node < N) ? batch[node] : -1;
    }
    __syncthreads();

    // --- fused matmul: thread t computes column t of [gate-H | local-L] for all M1 nodes ---
    unsigned long long acc[M1];
    #pragma unroll
    for (int m = 0; m < M1; m++) acc[m] = 0ULL;

    const ulonglong2* wp = (const ulonglong2*)g_wP;   // [d4*256 + tid]
    // Register double-buffer for the weight stream: prefetch w[d4+1] before
    // consuming w[d4] so the L2-hit latency (~250 cyc) is covered by a full
    // loop body. __ldg forces the non-coherent read-only LDG path. Tail
    // iteration peeled so the hot loop has no predication.
    ulonglong2 w = __ldg(&wp[tid]);
    #pragma unroll 2
    for (int d4 = 0; d4 < 63; d4++) {
        ulonglong2 wn = __ldg(&wp[(d4 + 1) * 256 + tid]);  // unconditional prefetch
        #pragma unroll
        for (int m = 0; m < M1; m++) {
            ulonglong2 xv = *(const ulonglong2*)(sX + m * 256 + d4 * 4);  // LDS.128 broadcast
            acc[m] = ffma2(xv.x, w.x, acc[m]);
            acc[m] = ffma2(xv.y, w.y, acc[m]);
        }
        w = wn;
    }
    {   // peeled last step (d4 = 63)
        #pragma unroll
        for (int m = 0; m < M1; m++) {
            ulonglong2 xv = *(const ulonglong2*)(sX + m * 256 + 63 * 4);
            acc[m] = ffma2(xv.x, w.x, acc[m]);
            acc[m] = ffma2(xv.y, w.y, acc[m]);
        }
    }

    const float bias = g_bs[tid];
    float locv[M1];                 // local-pool gelu values (tid>=HH only)

    // --- consume acc immediately (kills 64 regs before flush phase) ---
    if (tid < HH) {
        // gate hidden: v[m] = gelu(.)*w2[t]; transpose-reduce butterfly so that
        // after 5 stages lane l holds node l's sum in v[0]. All indices are
        // compile-time constants -> no local-memory demotion.
        const float w2t = w2[tid];
        float v[M1];
        #pragma unroll
        for (int m = 0; m < M1; m++) {
            float2 f = unpk(acc[m]);
            v[m] = gelu_exact(f.x + f.y + bias) * w2t;
        }
        #pragma unroll
        for (int k = 16; k >= 1; k >>= 1) {
            const bool up = (lane & k) != 0;
            #pragma unroll
            for (int i = 0; i < k; i++) {
                float give = up ? v[i] : v[i + k];       // half my partner keeps
                float got  = __shfl_xor_sync(0xffffffffu, give, k);
                v[i] = (up ? v[i + k] : v[i]) + got;     // half I keep + partner's
            }
        }
        sGp[lane * 4 + (tid >> 5)] = v[0];               // node=lane, warp partial
    } else {
        // local MLP gelu values, kept in registers for the later flush
        #pragma unroll
        for (int m = 0; m < M1; m++) {
            float2 f = unpk(acc[m]);
            locv[m] = gelu_exact(f.x + f.y + bias);
        }
    }
    __syncthreads();

    // --- finish gate: sE[m] = exp(gate_m)  (softmax is shift-invariant; gates
    // here are O(0.05) so the reference's max-subtraction is a no-op in exact
    // arithmetic and unnecessary for fp32 range) ---
    if (tid < M1) {
        float s = sGp[tid * 4 + 0] + sGp[tid * 4 + 1]
                + sGp[tid * 4 + 2] + sGp[tid * 4 + 3] + b2[0];
        sE[tid] = (sb[tid] >= 0) ? expf(s) : 0.0f;
    }
    __syncthreads();

    // --- per-feature run-length flush: mean, max, attention (e-weighted) ---
    {
        const int d = tid;
        float s  = 0.0f;                         // mean-sum
        float a  = 0.0f;                         // att-sum
        float mx = __int_as_float(0xff800000);   // -inf
        int   cur = sb[0];
        #pragma unroll
        for (int m = 0; m < M1; m++) {
            int sg = sb[m];
            if (sg != cur) {
                if (cur >= 0) {
                    atomicAdd(&out[cur * OC + d], s);
                    atomicMax((unsigned*)&out[cur * OC + DD + d], enc_f(mx));
                    atomicAdd(&out[cur * OC + 2 * DD + d], a);
                }
                s = 0.0f; a = 0.0f; mx = __int_as_float(0xff800000); cur = sg;
            }
            if (sg >= 0) {
                float v = sX[m * 256 + d];
                s += v;
                a  = fmaf(sE[m], v, a);
                mx = fmaxf(mx, v);
            }
        }
        if (cur >= 0) {
            atomicAdd(&out[cur * OC + d], s);
            atomicMax((unsigned*)&out[cur * OC + DD + d], enc_f(mx));
            atomicAdd(&out[cur * OC + 2 * DD + d], a);
        }
    }

    // --- local MLP pool: threads 128..255 own local columns ---
    if (tid >= HH) {
        const int c = tid - HH;
        float s = 0.0f; int cur = sb[0];
        #pragma unroll
        for (int m = 0; m < M1; m++) {
            int sg = sb[m];
            if (sg != cur) {
                if (cur >= 0) atomicAdd(&out[cur * OC + 3 * DD + c], s);
                s = 0.0f; cur = sg;
            }
            if (sg >= 0) s += locv[m];
        }
        if (cur >= 0) atomicAdd(&out[cur * OC + 3 * DD + c], s);
    }

    // --- counts (thread 0) and softmax denominators (thread 32) ---
    if (tid == 0) {
        float c = 0.0f; int cur = sb[0];
        #pragma unroll
        for (int m = 0; m < M1; m++) {
            int sg = sb[m];
            if (sg != cur) { if (cur >= 0) atomicAdd(&g_cnt[cur], c); c = 0.0f; cur = sg; }
            if (sg >= 0) c += 1.0f;
        }
        if (cur >= 0) atomicAdd(&g_cnt[cur], c);
    }
    if (tid == 32) {
        float s = 0.0f; int cur = sb[0];
        #pragma unroll
        for (int m = 0; m < M1; m++) {
            int sg = sb[m];
            if (sg != cur) { if (cur >= 0) atomicAdd(&g_denom[cur], s); s = 0.0f; cur = sg; }
            if (sg >= 0) s += sE[m];
        }
        if (cur >= 0) atomicAdd(&g_denom[cur], s);
    }
}

// ---------------- kernel 3: finalize (divides, decode max) ----------------
__global__ void k_final(float* __restrict__ out) {
    int i = blockIdx.x * blockDim.x + threadIdx.x;
    if (i >= GG * OC) return;
    int g = i / OC;
    int c = i % OC;
    float rcnt = 1.0f / fmaxf(g_cnt[g], 1.0f);
    if (c < DD) {
        out[i] = out[i] * rcnt;                     // mean
    } else if (c < 2 * DD) {
        out[i] = dec_f(((unsigned*)out)[i]);        // max (decode)
    } else if (c < 3 * DD) {
        float dn = g_denom[g];
        out[i] = (dn > 0.0f) ? out[i] / dn : 0.0f;  // attention
    } else {
        out[i] = out[i] * rcnt;                     // local mean
    }
}

// ---------------- launch ----------------
extern "C" void kernel_launch(void* const* d_in, const int* in_sizes, int n_in,
                              void* d_out, int out_size) {
    const float* x    = (const float*)d_in[0];
    const int*   batch= (const int*)  d_in[1];
    const float* w1   = (const float*)d_in[2];
    const float* b1   = (const float*)d_in[3];
    const float* w2   = (const float*)d_in[4];
    const float* b2   = (const float*)d_in[5];
    const float* lp_w = (const float*)d_in[6];
    const float* lp_b = (const float*)d_in[7];
    float* out = (float*)d_out;
    const int N = in_sizes[1];   // batch element count = node count

    int tot = GG * OC;
    k_init<<<(tot + 255) / 256, 256>>>(out);
    k_prep<<<64, 256>>>(w1, lp_w, b1, lp_b);
    k_fused<<<(N + M1 - 1) / M1, 256>>>(x, batch, w2, b2, out, N);
    k_final<<<(tot + 255) / 256, 256>>>(out);
}

// round 15
// speedup vs baseline: 2.3212x; 2.3212x over previous
#include <cuda_runtime.h>
#include <cstdint>

// Problem constants (match reference setup_inputs)
#define NN   500000
#define DD   256
#define GG   1024
#define HH   128
#define LL   128
#define OC   896      // 3*D + D/2
#define M1   32       // nodes per tile
#define XS   260      // sX row stride in floats (pad: bank = lane for mma A-frag loads)

// ---------------- device scratch (no cudaMalloc allowed) ----------------
__device__ float    g_denom[GG];
__device__ float    g_cnt[GG];
// B fragments packed in per-thread mma order (tf32 bits).
// float-index = ((warp*32 + s)*2 + h)*128 + lane*4 + e
__device__ __align__(16) unsigned g_wB[65536];
__device__ float    g_bs[256];           // [b1 ; lp_b]

// ---------------- helpers ----------------
__device__ __forceinline__ unsigned enc_f(float f) {
    unsigned u = __float_as_uint(f);
    return (u & 0x80000000u) ? ~u : (u | 0x80000000u);
}
__device__ __forceinline__ float dec_f(unsigned u) {
    return (u & 0x80000000u) ? __uint_as_float(u & 0x7FFFFFFFu)
                             : __uint_as_float(~u);
}
#define ENC_NEG_INF 0x007FFFFFu

__device__ __forceinline__ float gelu_exact(float z) {
    return 0.5f * z * (1.0f + erff(z * 0.7071067811865476f));
}
__device__ __forceinline__ unsigned cvt_tf32(float f) {
    unsigned o;
    asm("cvt.rna.tf32.f32 %0, %1;" : "=r"(o) : "f"(f));
    return o;
}
// m16n8k8 row.col f32 += tf32 * tf32
__device__ __forceinline__ void mma1688(float* c, const unsigned* a, const unsigned* b) {
    asm volatile(
        "mma.sync.aligned.m16n8k8.row.col.f32.tf32.tf32.f32 "
        "{%0,%1,%2,%3}, {%4,%5,%6,%7}, {%8,%9}, {%0,%1,%2,%3};"
        : "+f"(c[0]), "+f"(c[1]), "+f"(c[2]), "+f"(c[3])
        : "r"(a[0]), "r"(a[1]), "r"(a[2]), "r"(a[3]), "r"(b[0]), "r"(b[1]));
}

// ---------------- kernel 0: init accumulators ----------------
__global__ void k_init(float* __restrict__ out) {
    int i = blockIdx.x * blockDim.x + threadIdx.x;
    int total = GG * OC;
    if (i < total) {
        int c = i % OC;
        if (c >= DD && c < 2 * DD)
            ((unsigned*)out)[i] = ENC_NEG_INF;
        else
            out[i] = 0.0f;
    }
    if (i < GG) { g_cnt[i] = 0.0f; g_denom[i] = 0.0f; }
}

// ---------------- kernel T: pack B fragments + biases ----------------
// idx -> (w,s,h,lane,e):  j = h*2 + (e>>1), r = e&1,
//   d (= k-index) = 8s + (lane&3) + 4r,  col (= n) = 32w + 8j + (lane>>2)
// which is exactly the mma.m16n8k8 col-major B fragment ordering.
__global__ void k_prep(const float* __restrict__ w1, const float* __restrict__ lp_w,
                       const float* __restrict__ b1, const float* __restrict__ lp_b) {
    int idx  = blockIdx.x * 256 + threadIdx.x;    // 0..65535
    int e    = idx & 3;
    int lane = (idx >> 2) & 31;
    int h    = (idx >> 7) & 1;
    int s    = (idx >> 8) & 31;
    int w    = idx >> 13;
    int j    = h * 2 + (e >> 1);
    int r    = e & 1;
    int d    = 8 * s + (lane & 3) + 4 * r;
    int col  = 32 * w + 8 * j + (lane >> 2);
    float v  = (col < HH) ? w1[d * HH + col] : lp_w[d * LL + (col - HH)];
    g_wB[idx] = cvt_tf32(v);
    if (idx < 256)
        g_bs[idx] = (idx < HH) ? b1[idx] : lp_b[idx - HH];
}

// ---------------- fused kernel: tensor-core MLPs + all four pools --------
// Static shared: sX 32*260*4=33280 + sGate 128 + sE 128 + sb 128 = 33664 B.
__global__ __launch_bounds__(256, 2)
void k_fused(const float* __restrict__ x, const int* __restrict__ batch,
             const float* __restrict__ w2, const float* __restrict__ b2,
             float* __restrict__ out, int N) {
    __shared__ __align__(16) float sX[M1 * XS];
    __shared__ float sGate[M1];
    __shared__ float sE[M1];
    __shared__ int   sb[M1];

    const int  tid  = threadIdx.x;
    const int  lane = tid & 31;
    const int  warp = tid >> 5;          // 0..7; warp owns out-cols [32w, 32w+32)
    const long base = (long)blockIdx.x * M1;

    // --- load x tile (float4, coalesced, 65 float4 per row incl. pad) ---
    for (int i = tid; i < M1 * 64; i += 256) {
        int  m    = i >> 6;
        int  q    = i & 63;
        long node = base + m;
        float4 v  = make_float4(0.f, 0.f, 0.f, 0.f);
        if (node < N) v = ((const float4*)x)[node * 64 + q];
        ((float4*)sX)[m * 65 + q] = v;
    }
    if (tid < M1) {
        long node = base + tid;
        sb[tid] = (node < N) ? batch[node] : -1;
        sGate[tid] = 0.0f;
    }
    __syncthreads();

    // --- tensor-core matmul: D[32 nodes x 32 cols-per-warp], K=256 ---
    float acc[2][4][4];
    #pragma unroll
    for (int mi = 0; mi < 2; mi++)
        #pragma unroll
        for (int j = 0; j < 4; j++)
            #pragma unroll
            for (int q = 0; q < 4; q++) acc[mi][j][q] = 0.0f;

    const uint4* wb4 = (const uint4*)g_wB;
    #pragma unroll 4
    for (int s = 0; s < 32; s++) {
        uint4 f0 = __ldg(&wb4[((warp * 32 + s) * 2 + 0) * 32 + lane]);
        uint4 f1 = __ldg(&wb4[((warp * 32 + s) * 2 + 1) * 32 + lane]);
        unsigned b[4][2] = {{f0.x, f0.y}, {f0.z, f0.w}, {f1.x, f1.y}, {f1.z, f1.w}};

        const int c0 = 8 * s + (lane & 3);
        unsigned a[2][4];
        #pragma unroll
        for (int mi = 0; mi < 2; mi++) {
            int r0 = (lane >> 2) + 16 * mi;
            a[mi][0] = cvt_tf32(sX[r0 * XS + c0]);
            a[mi][1] = cvt_tf32(sX[(r0 + 8) * XS + c0]);
            a[mi][2] = cvt_tf32(sX[r0 * XS + c0 + 4]);
            a[mi][3] = cvt_tf32(sX[(r0 + 8) * XS + c0 + 4]);
        }
        #pragma unroll
        for (int mi = 0; mi < 2; mi++)
            #pragma unroll
            for (int j = 0; j < 4; j++)
                mma1688(acc[mi][j], a[mi], b[j]);
    }

    // --- epilogue: biases (+ w2 for gate warps) for this thread's 8 cols ---
    // c[0]@(row, col0) c[1]@(row, col0+1) c[2]@(row+8, col0) c[3]@(row+8, col0+1)
    // row = (lane>>2) + 16*mi, col0 = 32*warp + 8*j + 2*(lane&3)
    float bias0[4], bias1[4], w2a[4], w2b[4];
    #pragma unroll
    for (int j = 0; j < 4; j++) {
        int col0 = 32 * warp + 8 * j + 2 * (lane & 3);
        bias0[j] = g_bs[col0];
        bias1[j] = g_bs[col0 + 1];
        if (warp < 4) { w2a[j] = w2[col0]; w2b[j] = w2[col0 + 1]; }
    }

    if (warp < 4) {
        // gate: per-row partial sums of gelu(pre)*w2 over this warp's 32 cols
        float rowsum[4] = {0.f, 0.f, 0.f, 0.f};   // rows g, g+8, g+16, g+24
        #pragma unroll
        for (int mi = 0; mi < 2; mi++)
            #pragma unroll
            for (int j = 0; j < 4; j++) {
                rowsum[2 * mi]     += gelu_exact(acc[mi][j][0] + bias0[j]) * w2a[j]
                                    + gelu_exact(acc[mi][j][1] + bias1[j]) * w2b[j];
                rowsum[2 * mi + 1] += gelu_exact(acc[mi][j][2] + bias0[j]) * w2a[j]
                                    + gelu_exact(acc[mi][j][3] + bias1[j]) * w2b[j];
            }
        #pragma unroll
        for (int k = 1; k <= 2; k <<= 1)
            #pragma unroll
            for (int i = 0; i < 4; i++)
                rowsum[i] += __shfl_xor_sync(0xffffffffu, rowsum[i], k);
        if ((lane & 3) == 0) {
            int r = lane >> 2;
            #pragma unroll
            for (int i = 0; i < 4; i++)
                atomicAdd(&sGate[r + 8 * i], rowsum[i]);
        }
    } else {
        // local pool: gelu then per-element segment atomic add (spread addrs)
        #pragma unroll
        for (int mi = 0; mi < 2; mi++)
            #pragma unroll
            for (int j = 0; j < 4; j++) {
                int col0 = 32 * warp + 8 * j + 2 * (lane & 3) - HH;   // local col
                int rA = (lane >> 2) + 16 * mi;
                int rB = rA + 8;
                int sgA = sb[rA], sgB = sb[rB];
                if (sgA >= 0) {
                    atomicAdd(&out[sgA * OC + 3 * DD + col0],     gelu_exact(acc[mi][j][0] + bias0[j]));
                    atomicAdd(&out[sgA * OC + 3 * DD + col0 + 1], gelu_exact(acc[mi][j][1] + bias1[j]));
                }
                if (sgB >= 0) {
                    atomicAdd(&out[sgB * OC + 3 * DD + col0],     gelu_exact(acc[mi][j][2] + bias0[j]));
                    atomicAdd(&out[sgB * OC + 3 * DD + col0 + 1], gelu_exact(acc[mi][j][3] + bias1[j]));
                }
            }
    }
    __syncthreads();

    // --- sE[m] = exp(gate)  (softmax shift-invariant; gates are O(0.05)) ---
    if (tid < M1)
        sE[tid] = (sb[tid] >= 0) ? expf(sGate[tid] + b2[0]) : 0.0f;
    __syncthreads();

    // --- per-feature run-length flush: mean, max, attention ---
    {
        const int d = tid;
        float s  = 0.0f;
        float a  = 0.0f;
        float mx = __int_as_float(0xff800000);
        int   cur = sb[0];
        #pragma unroll
        for (int m = 0; m < M1; m++) {
            int sg = sb[m];
            if (sg != cur) {
                if (cur >= 0) {
                    atomicAdd(&out[cur * OC + d], s);
                    atomicMax((unsigned*)&out[cur * OC + DD + d], enc_f(mx));
                    atomicAdd(&out[cur * OC + 2 * DD + d], a);
                }
                s = 0.0f; a = 0.0f; mx = __int_as_float(0xff800000); cur = sg;
            }
            if (sg >= 0) {
                float v = sX[m * XS + d];
                s += v;
                a  = fmaf(sE[m], v, a);
                mx = fmaxf(mx, v);
            }
        }
        if (cur >= 0) {
            atomicAdd(&out[cur * OC + d], s);
            atomicMax((unsigned*)&out[cur * OC + DD + d], enc_f(mx));
            atomicAdd(&out[cur * OC + 2 * DD + d], a);
        }
    }

    // --- counts (thread 0) and softmax denominators (thread 32) ---
    if (tid == 0) {
        float c = 0.0f; int cur = sb[0];
        #pragma unroll
        for (int m = 0; m < M1; m++) {
            int sg = sb[m];
            if (sg != cur) { if (cur >= 0) atomicAdd(&g_cnt[cur], c); c = 0.0f; cur = sg; }
            if (sg >= 0) c += 1.0f;
        }
        if (cur >= 0) atomicAdd(&g_cnt[cur], c);
    }
    if (tid == 32) {
        float s = 0.0f; int cur = sb[0];
        #pragma unroll
        for (int m = 0; m < M1; m++) {
            int sg = sb[m];
            if (sg != cur) { if (cur >= 0) atomicAdd(&g_denom[cur], s); s = 0.0f; cur = sg; }
            if (sg >= 0) s += sE[m];
        }
        if (cur >= 0) atomicAdd(&g_denom[cur], s);
    }
}

// ---------------- kernel 3: finalize ----------------
__global__ void k_final(float* __restrict__ out) {
    int i = blockIdx.x * blockDim.x + threadIdx.x;
    if (i >= GG * OC) return;
    int g = i / OC;
    int c = i % OC;
    float rcnt = 1.0f / fmaxf(g_cnt[g], 1.0f);
    if (c < DD) {
        out[i] = out[i] * rcnt;
    } else if (c < 2 * DD) {
        out[i] = dec_f(((unsigned*)out)[i]);
    } else if (c < 3 * DD) {
        float dn = g_denom[g];
        out[i] = (dn > 0.0f) ? out[i] / dn : 0.0f;
    } else {
        out[i] = out[i] * rcnt;
    }
}

// ---------------- launch ----------------
extern "C" void kernel_launch(void* const* d_in, const int* in_sizes, int n_in,
                              void* d_out, int out_size) {
    const float* x    = (const float*)d_in[0];
    const int*   batch= (const int*)  d_in[1];
    const float* w1   = (const float*)d_in[2];
    const float* b1   = (const float*)d_in[3];
    const float* w2   = (const float*)d_in[4];
    const float* b2   = (const float*)d_in[5];
    const float* lp_w = (const float*)d_in[6];
    const float* lp_b = (const float*)d_in[7];
    float* out = (float*)d_out;
    const int N = in_sizes[1];

    int tot = GG * OC;
    k_init<<<(tot + 255) / 256, 256>>>(out);
    k_prep<<<256, 256>>>(w1, lp_w, b1, lp_b);
    k_fused<<<(N + M1 - 1) / M1, 256>>>(x, batch, w2, b2, out, N);
    k_final<<<(tot + 255) / 256, 256>>>(out);
}